// round 3
// baseline (speedup 1.0000x reference)
#include <cuda_runtime.h>
#include <cuda_bf16.h>
#include <math.h>

// Problem constants
#define B_SZ 512
#define K_SZ 32
#define D_SZ 768
#define N_SENSES 200000
#define NEG_INF -1e30f

// Scratch for per-sample NLL + completion counter.
// atomicInc with wrap B_SZ-1 self-resets to 0 after every full launch,
// so graph replays stay deterministic without an init kernel.
__device__ float g_nll[B_SZ];
__device__ unsigned g_done = 0;

// One CTA per sample. 32 warps; warp w computes the logit for candidate w.
// The last CTA to finish performs the deterministic tree-sum of all NLLs.
__global__ __launch_bounds__(1024, 1)
void cbert_fused_kernel(const float* __restrict__ reps,
                        const float* __restrict__ weight,
                        const float* __restrict__ bias,
                        const int* __restrict__ sense_ids,
                        const int* __restrict__ target_ids,
                        float* __restrict__ out, int out_size) {
    const int b = blockIdx.x;
    const int tid = threadIdx.x;
    const int wid = tid >> 5;   // warp id == candidate k
    const int lane = tid & 31;

    __shared__ float s_reps[D_SZ];        // 3 KB; reused for final reduction
    __shared__ float s_logits[K_SZ];
    __shared__ bool s_last;

    // Stage reps[b] into smem: 768 floats = 192 float4
    {
        const float4* src = reinterpret_cast<const float4*>(reps + (size_t)b * D_SZ);
        float4* dst = reinterpret_cast<float4*>(s_reps);
        if (tid < D_SZ / 4) dst[tid] = src[tid];
    }
    __syncthreads();

    // Each warp: dot(weight[id], reps[b]) + bias[id], or NEG_INF if padded
    const int id = sense_ids[b * K_SZ + wid];
    float logit = NEG_INF;
    if (id >= 0 && id < N_SENSES) {
        const float4* wrow = reinterpret_cast<const float4*>(weight + (size_t)id * D_SZ);
        const float4* rrow = reinterpret_cast<const float4*>(s_reps);
        float acc = 0.f;
        // 192 float4 per row, 32 lanes -> 6 float4 per lane (MLP=6)
        #pragma unroll
        for (int j = 0; j < 6; ++j) {
            const int i = lane + 32 * j;
            float4 w4 = wrow[i];
            float4 r4 = rrow[i];
            acc = fmaf(w4.x, r4.x, acc);
            acc = fmaf(w4.y, r4.y, acc);
            acc = fmaf(w4.z, r4.z, acc);
            acc = fmaf(w4.w, r4.w, acc);
        }
        #pragma unroll
        for (int off = 16; off > 0; off >>= 1)
            acc += __shfl_down_sync(0xFFFFFFFFu, acc, off);
        if (lane == 0) logit = acc + bias[id];
    }
    if (lane == 0) s_logits[wid] = logit;
    __syncthreads();

    // Warp 0: masked softmax over 32 logits, NLL + argmax-correct
    if (wid == 0) {
        float v = s_logits[lane];

        // max + first-index argmax (larger val wins; tie -> smaller idx)
        float mval = v; int midx = lane;
        #pragma unroll
        for (int off = 16; off > 0; off >>= 1) {
            float ov = __shfl_down_sync(0xFFFFFFFFu, mval, off);
            int   oi = __shfl_down_sync(0xFFFFFFFFu, midx, off);
            if (ov > mval || (ov == mval && oi < midx)) { mval = ov; midx = oi; }
        }
        mval = __shfl_sync(0xFFFFFFFFu, mval, 0);
        midx = __shfl_sync(0xFFFFFFFFu, midx, 0);

        float e = expf(v - mval);
        #pragma unroll
        for (int off = 16; off > 0; off >>= 1)
            e += __shfl_down_sync(0xFFFFFFFFu, e, off);
        float sumexp = __shfl_sync(0xFFFFFFFFu, e, 0);

        const int tgt = target_ids[b];
        float tlogit = __shfl_sync(0xFFFFFFFFu, v, tgt & 31);

        if (lane == 0) {
            float nll = -(tlogit - mval - logf(sumexp));
            g_nll[b] = nll;
            if (1 + b < out_size) out[1 + b] = (midx == tgt) ? 1.0f : 0.0f;
            // Publish, then count this CTA as done. Wrap at B_SZ-1 so the
            // counter returns to 0 after the full grid -> replay-safe.
            __threadfence();
            unsigned old = atomicInc(&g_done, B_SZ - 1);
            s_last = (old == B_SZ - 1);
        }
    }
    __syncthreads();

    // Last CTA: deterministic fixed-order tree sum of all 512 NLLs.
    if (s_last) {
        if (tid < B_SZ) s_reps[tid] = __ldcg(&g_nll[tid]);  // bypass L1
        __syncthreads();
        #pragma unroll
        for (int off = B_SZ / 2; off > 0; off >>= 1) {
            if (tid < off) s_reps[tid] += s_reps[tid + off];
            __syncthreads();
        }
        if (tid == 0 && out_size > 0) out[0] = s_reps[0] / (float)B_SZ;
    }
}

extern "C" void kernel_launch(void* const* d_in, const int* in_sizes, int n_in,
                              void* d_out, int out_size) {
    const float* reps = (const float*)d_in[0];
    const float* weight = (const float*)d_in[1];
    const float* bias = (const float*)d_in[2];
    const int* sense_ids = (const int*)d_in[3];
    const int* target_ids = (const int*)d_in[4];
    float* out = (float*)d_out;

    cbert_fused_kernel<<<B_SZ, 1024>>>(reps, weight, bias, sense_ids, target_ids,
                                       out, out_size);
}